// round 1
// baseline (speedup 1.0000x reference)
#include <cuda_runtime.h>
#include <cuda_bf16.h>

#define BB 32
#define TT 2048
#define II 256
#define HH 512
#define GG 2048   // 4*H

#define NCTA 128
#define NTH  256

// Scratch (device globals — no runtime allocation allowed)
__device__ float g_xg[134217728];          // [T][B][4H] = 2048*32*2048 floats (512 MB)
__device__ float g_h[2][BB * HH];          // ping-pong hidden state
__device__ int   g_bar;                    // monotonic barrier counter

// ---------------------------------------------------------------------------
// Kernel A: xg[t*B+b][g] = sum_i x[b][t][i]*W_ih[g][i] + b_ih[g] + b_hh[g]
// 64x64 tile, K-chunk 16, 256 threads, 4x4 micro-tile.
// ---------------------------------------------------------------------------
__global__ void __launch_bounds__(256) xg_gemm_kernel(
    const float* __restrict__ x,
    const float* __restrict__ Wih,
    const float* __restrict__ bih,
    const float* __restrict__ bhh)
{
    __shared__ float a_sm[16][64];
    __shared__ float b_sm[16][64];

    const int tid = threadIdx.x;
    if (blockIdx.x == 0 && blockIdx.y == 0 && tid == 0) g_bar = 0;  // reset barrier for kernel B

    const int row0 = blockIdx.y * 64;           // over M = T*B
    const int col0 = blockIdx.x * 64;           // over G = 4H
    const int tx = tid & 15;                    // n-quad
    const int ty = tid >> 4;                    // m-quad

    const int lrow = tid & 63;                  // loader row within tile
    const int kq   = tid >> 6;                  // loader k-quad (0..3)

    const int r = row0 + lrow;                  // global M row: r = t*B + b
    const int b = r & (BB - 1);
    const int t = r >> 5;                       // B = 32
    const float* xrow = x + ((size_t)b * TT + t) * II;
    const float* wrow = Wih + (size_t)(col0 + lrow) * II;

    float acc[4][4] = {};

    for (int k0 = 0; k0 < II; k0 += 16) {
        float4 av = *(const float4*)(xrow + k0 + 4 * kq);
        float4 bv = *(const float4*)(wrow + k0 + 4 * kq);
        __syncthreads();
        a_sm[4 * kq + 0][lrow] = av.x;
        a_sm[4 * kq + 1][lrow] = av.y;
        a_sm[4 * kq + 2][lrow] = av.z;
        a_sm[4 * kq + 3][lrow] = av.w;
        b_sm[4 * kq + 0][lrow] = bv.x;
        b_sm[4 * kq + 1][lrow] = bv.y;
        b_sm[4 * kq + 2][lrow] = bv.z;
        b_sm[4 * kq + 3][lrow] = bv.w;
        __syncthreads();
#pragma unroll
        for (int kk = 0; kk < 16; kk++) {
            float4 a4 = *(const float4*)&a_sm[kk][ty * 4];
            float4 b4 = *(const float4*)&b_sm[kk][tx * 4];
            float aa[4] = {a4.x, a4.y, a4.z, a4.w};
            float bb[4] = {b4.x, b4.y, b4.z, b4.w};
#pragma unroll
            for (int i = 0; i < 4; i++)
#pragma unroll
                for (int j = 0; j < 4; j++)
                    acc[i][j] = fmaf(aa[i], bb[j], acc[i][j]);
        }
    }

    const int g0 = col0 + tx * 4;
    float4 bi = *(const float4*)(bih + g0);
    float4 bh = *(const float4*)(bhh + g0);
    float bias[4] = {bi.x + bh.x, bi.y + bh.y, bi.z + bh.z, bi.w + bh.w};
#pragma unroll
    for (int i = 0; i < 4; i++) {
        int row = row0 + ty * 4 + i;
        float4 o;
        o.x = acc[i][0] + bias[0];
        o.y = acc[i][1] + bias[1];
        o.z = acc[i][2] + bias[2];
        o.w = acc[i][3] + bias[3];
        *(float4*)(g_xg + (size_t)row * GG + g0) = o;
    }
}

// ---------------------------------------------------------------------------
// Kernel B: persistent recurrence. 128 CTAs x 256 threads.
// CTA c owns hidden columns [4c, 4c+4); 16 gate rows (i,f,g,o per column).
// Per step: load full h into smem; each thread computes 2 dot products
// (one gate row x 2 batches, K=512); activations; global h exchange; barrier.
// ---------------------------------------------------------------------------
__device__ __forceinline__ float sigf(float v) {
    return 1.0f / (1.0f + __expf(-v));
}

__global__ void __launch_bounds__(NTH, 1) lstm_rec_kernel(
    const float* __restrict__ Whh,
    const float* __restrict__ h0,
    const float* __restrict__ c0,
    float* __restrict__ out,
    long long out_size)
{
    extern __shared__ float smem[];
    float4* h4 = (float4*)smem;                       // [32][128]   (64 KB)
    float4* w4 = h4 + BB * 128;                       // [16][129]   (33 KB, padded)
    float*  gates = (float*)(w4 + 16 * 129);          // [16][33]    (padded stride)
    float*  csm = gates + 16 * 33;                    // [32*4]

    const int tid = threadIdx.x;
    const int cta = blockIdx.x;
    const int col0 = cta * 4;

    // Load W_hh slice into smem (once). Row r: gate = r>>2, cj = r&3.
    for (int idx = tid; idx < 16 * 128; idx += NTH) {
        int r = idx >> 7;
        int q = idx & 127;
        int grow = (r >> 2) * HH + col0 + (r & 3);
        w4[r * 129 + q] = *(const float4*)(Whh + (size_t)grow * HH + 4 * q);
    }
    // Init cell state for this CTA's 4 columns.
    if (tid < 128) {
        int cj = tid & 3;
        int b = tid >> 2;
        csm[tid] = c0[b * HH + col0 + cj];
    }
    __syncthreads();

    // GEMM thread identity: 2 outputs (gate row r, batches b0 and b0+1)
    const int r = tid & 15;
    const int b0 = (tid >> 4) * 2;
    const int grow = (r >> 2) * HH + col0 + (r & 3);

    const long long BTH = (long long)BB * TT * HH;
    const bool tails = (out_size >= BTH + 2LL * BB * HH);

    volatile int* vbar = &g_bar;

    for (int t = 0; t < TT; t++) {
        // Prefetch xg contributions for this thread's 2 outputs.
        float xg0 = g_xg[((size_t)t * BB + b0) * GG + grow];
        float xg1 = g_xg[((size_t)t * BB + b0 + 1) * GG + grow];

        // Load h (global -> smem).
        const float4* hsrc = (t == 0) ? (const float4*)h0 : (const float4*)g_h[t & 1];
        for (int idx = tid; idx < BB * 128; idx += NTH) h4[idx] = hsrc[idx];
        __syncthreads();

        // Dot products: K = 512 (128 float4 steps)
        float acc0 = 0.0f, acc1 = 0.0f;
        const float4* wr  = &w4[r * 129];
        const float4* ha4 = &h4[b0 * 128];
        const float4* hb4 = &h4[(b0 + 1) * 128];
#pragma unroll 16
        for (int q = 0; q < 128; q++) {
            float4 w = wr[q];
            float4 ha = ha4[q];
            float4 hb = hb4[q];
            acc0 = fmaf(w.x, ha.x, acc0);
            acc0 = fmaf(w.y, ha.y, acc0);
            acc0 = fmaf(w.z, ha.z, acc0);
            acc0 = fmaf(w.w, ha.w, acc0);
            acc1 = fmaf(w.x, hb.x, acc1);
            acc1 = fmaf(w.y, hb.y, acc1);
            acc1 = fmaf(w.z, hb.z, acc1);
            acc1 = fmaf(w.w, hb.w, acc1);
        }
        gates[r * 33 + b0]     = acc0 + xg0;
        gates[r * 33 + b0 + 1] = acc1 + xg1;
        __syncthreads();

        // Activations + state update: 128 threads (4 cols x 32 batches)
        if (tid < 128) {
            int cj = tid & 3;
            int b = tid >> 2;
            float gi = gates[(0  + cj) * 33 + b];
            float gf = gates[(4  + cj) * 33 + b];
            float gg = gates[(8  + cj) * 33 + b];
            float go = gates[(12 + cj) * 33 + b];
            float ig = sigf(gi);
            float fg = sigf(gf);
            float gt = tanhf(gg);
            float og = sigf(go);
            float cn = fmaf(fg, csm[tid], ig * gt);
            float hn = og * tanhf(cn);
            csm[tid] = cn;
            int col = col0 + cj;
            g_h[(t + 1) & 1][b * HH + col] = hn;
            out[((size_t)b * TT + t) * HH + col] = hn;
            if (t == TT - 1 && tails) {
                out[BTH + (long long)b * HH + col] = hn;
                out[BTH + (long long)BB * HH + (long long)b * HH + col] = cn;
            }
        }
        __threadfence();
        __syncthreads();
        // Grid barrier: monotonic counter (reset by kernel A each launch).
        if (tid == 0) {
            atomicAdd(&g_bar, 1);
            int target = NCTA * (t + 1);
            while (*vbar < target) __nanosleep(32);
            __threadfence();
        }
        __syncthreads();
    }
}

// ---------------------------------------------------------------------------
// Inputs (metadata order): x, h0, c0, W_ih, W_hh, b_ih, b_hh
// Output: concat(result[B,T,H], h_f[1,B,H], c_f[1,B,H])
// ---------------------------------------------------------------------------
extern "C" void kernel_launch(void* const* d_in, const int* in_sizes, int n_in,
                              void* d_out, int out_size) {
    const float* x   = (const float*)d_in[0];
    const float* h0  = (const float*)d_in[1];
    const float* c0  = (const float*)d_in[2];
    const float* Wih = (const float*)d_in[3];
    const float* Whh = (const float*)d_in[4];
    const float* bih = (const float*)d_in[5];
    const float* bhh = (const float*)d_in[6];
    float* out = (float*)d_out;

    // Dynamic smem for the persistent kernel: h(64KB) + W(33KB) + gates + c
    const int smem_b = (BB * 128 + 16 * 129) * 16 + (16 * 33 + 128) * 4;
    cudaFuncSetAttribute(lstm_rec_kernel, cudaFuncAttributeMaxDynamicSharedMemorySize, smem_b);

    dim3 gridA(GG / 64, (TT * BB) / 64);
    xg_gemm_kernel<<<gridA, 256>>>(x, Wih, bih, bhh);
    lstm_rec_kernel<<<NCTA, NTH, smem_b>>>(Whh, h0, c0, out, (long long)out_size);
}

// round 2
// speedup vs baseline: 2.0209x; 2.0209x over previous
#include <cuda_runtime.h>
#include <cuda_bf16.h>

#define BB 32
#define TT 2048
#define II 256
#define HH 512
#define GG 2048   // 4*H

#define NCTA 128
#define NTH  256

// Scratch (device globals — no runtime allocation allowed)
__device__ float g_xg[134217728];          // [T][B][4H] = 2048*32*2048 floats (512 MB)
__device__ float g_h[2][BB * HH];          // ping-pong hidden state
__device__ int   g_bar;                    // monotonic barrier counter

// ---------------------------------------------------------------------------
// Kernel A: xg[t*B+b][g] = sum_i x[b][t][i]*W_ih[g][i] + b_ih[g] + b_hh[g]
// 64x64 tile, K-chunk 16, 256 threads, 4x4 micro-tile. (unchanged)
// ---------------------------------------------------------------------------
__global__ void __launch_bounds__(256) xg_gemm_kernel(
    const float* __restrict__ x,
    const float* __restrict__ Wih,
    const float* __restrict__ bih,
    const float* __restrict__ bhh)
{
    __shared__ float a_sm[16][64];
    __shared__ float b_sm[16][64];

    const int tid = threadIdx.x;
    if (blockIdx.x == 0 && blockIdx.y == 0 && tid == 0) g_bar = 0;  // reset barrier for kernel B

    const int row0 = blockIdx.y * 64;           // over M = T*B
    const int col0 = blockIdx.x * 64;           // over G = 4H
    const int tx = tid & 15;                    // n-quad
    const int ty = tid >> 4;                    // m-quad

    const int lrow = tid & 63;                  // loader row within tile
    const int kq   = tid >> 6;                  // loader k-quad (0..3)

    const int r = row0 + lrow;                  // global M row: r = t*B + b
    const int b = r & (BB - 1);
    const int t = r >> 5;                       // B = 32
    const float* xrow = x + ((size_t)b * TT + t) * II;
    const float* wrow = Wih + (size_t)(col0 + lrow) * II;

    float acc[4][4] = {};

    for (int k0 = 0; k0 < II; k0 += 16) {
        float4 av = *(const float4*)(xrow + k0 + 4 * kq);
        float4 bv = *(const float4*)(wrow + k0 + 4 * kq);
        __syncthreads();
        a_sm[4 * kq + 0][lrow] = av.x;
        a_sm[4 * kq + 1][lrow] = av.y;
        a_sm[4 * kq + 2][lrow] = av.z;
        a_sm[4 * kq + 3][lrow] = av.w;
        b_sm[4 * kq + 0][lrow] = bv.x;
        b_sm[4 * kq + 1][lrow] = bv.y;
        b_sm[4 * kq + 2][lrow] = bv.z;
        b_sm[4 * kq + 3][lrow] = bv.w;
        __syncthreads();
#pragma unroll
        for (int kk = 0; kk < 16; kk++) {
            float4 a4 = *(const float4*)&a_sm[kk][ty * 4];
            float4 b4 = *(const float4*)&b_sm[kk][tx * 4];
            float aa[4] = {a4.x, a4.y, a4.z, a4.w};
            float bb[4] = {b4.x, b4.y, b4.z, b4.w};
#pragma unroll
            for (int i = 0; i < 4; i++)
#pragma unroll
                for (int j = 0; j < 4; j++)
                    acc[i][j] = fmaf(aa[i], bb[j], acc[i][j]);
        }
    }

    const int g0 = col0 + tx * 4;
    float4 bi = *(const float4*)(bih + g0);
    float4 bh = *(const float4*)(bhh + g0);
    float bias[4] = {bi.x + bh.x, bi.y + bh.y, bi.z + bh.z, bi.w + bh.w};
#pragma unroll
    for (int i = 0; i < 4; i++) {
        int row = row0 + ty * 4 + i;
        float4 o;
        o.x = acc[i][0] + bias[0];
        o.y = acc[i][1] + bias[1];
        o.z = acc[i][2] + bias[2];
        o.w = acc[i][3] + bias[3];
        *(float4*)(g_xg + (size_t)row * GG + g0) = o;
    }
}

// ---------------------------------------------------------------------------
// f32x2 packed-FMA helpers (sm_103a FFMA2; ptxas never auto-fuses these)
// ---------------------------------------------------------------------------
__device__ __forceinline__ unsigned long long fma2(
    unsigned long long a, unsigned long long b, unsigned long long c)
{
    unsigned long long d;
    asm("fma.rn.f32x2 %0, %1, %2, %3;" : "=l"(d) : "l"(a), "l"(b), "l"(c));
    return d;
}
__device__ __forceinline__ void upk2(unsigned long long v, float& x, float& y) {
    asm("mov.b64 {%0, %1}, %2;" : "=f"(x), "=f"(y) : "l"(v));
}

__device__ __forceinline__ float sigf(float v) {
    return 1.0f / (1.0f + __expf(-v));
}

// ---------------------------------------------------------------------------
// Kernel B: persistent recurrence. 128 CTAs x 256 threads.
// CTA c owns hidden columns [4c, 4c+4) -> 16 gate rows x 32 batches = 512 outs.
// Per step:
//   - load h (global->smem, padded stride 129 float4)
//   - GEMM: 8 warps split K (64 each); lane tile = 2 rows x 8 batches,
//     batches b = 4j + (lane&3); all math in packed f32x2 FFMA2.
//   - split-K reduction via smem (conflict-free layout), + xg, activations
//   - publish h, grid barrier (monotonic atomic counter)
// ---------------------------------------------------------------------------
__global__ void __launch_bounds__(NTH, 1) lstm_rec_kernel(
    const float* __restrict__ Whh,
    const float* __restrict__ h0,
    const float* __restrict__ c0,
    float* __restrict__ out,
    long long out_size)
{
    extern __shared__ float smem[];
    float4* h4 = (float4*)smem;                        // [32][129] float4 (66048 B)
    float4* w4 = h4 + 32 * 129;                        // [16][129] float4 (33024 B)
    float*  red = (float*)(w4 + 16 * 129);             // [8][16*34] floats (17408 B)
    float*  gates = red + 8 * 16 * 34;                 // [16][33]
    float*  csm = gates + 16 * 33;                     // [128]

    const int tid = threadIdx.x;
    const int cta = blockIdx.x;
    const int col0 = cta * 4;

    // Load W_hh slice into smem (once). Row r: gate = r>>2, cj = r&3.
    for (int idx = tid; idx < 16 * 128; idx += NTH) {
        int r = idx >> 7;
        int q = idx & 127;
        int grow = (r >> 2) * HH + col0 + (r & 3);
        w4[r * 129 + q] = *(const float4*)(Whh + (size_t)grow * HH + 4 * q);
    }
    // Init cell state for this CTA's 4 columns.
    if (tid < 128) {
        int cj = tid & 3;
        int b = tid >> 2;
        csm[tid] = c0[b * HH + col0 + cj];
    }
    __syncthreads();

    // GEMM identity
    const int wrp = tid >> 5;              // warp 0..7 -> K slice [64w, 64w+64)
    const int l   = tid & 31;
    const int rr  = l >> 2;                // 0..7
    const int br  = l & 3;                 // 0..3
    const int r0  = 2 * rr;
    const int r1  = r0 + 1;
    const int q0  = wrp * 16;              // float4 chunk base

    // Phase-2 identity: thread owns outputs o = 2*tid, 2*tid+1 (o = r*32+b)
    const int o0 = 2 * tid, o1 = o0 + 1;
    const int p2r0 = o0 >> 5, p2b0 = o0 & 31;
    const int p2r1 = o1 >> 5, p2b1 = o1 & 31;
    const int xgrow0 = (p2r0 >> 2) * HH + col0 + (p2r0 & 3);
    const int xgrow1 = (p2r1 >> 2) * HH + col0 + (p2r1 & 3);

    const long long BTH = (long long)BB * TT * HH;
    const bool tails = (out_size >= BTH + 2LL * BB * HH);

    volatile int* vbar = &g_bar;

    const float4* wp0 = w4 + r0 * 129 + q0;
    const float4* wp1 = w4 + r1 * 129 + q0;
    const float4* hp  = h4 + br * 129 + q0;   // batch (4j+br) => + j*516

    for (int t = 0; t < TT; t++) {
        // Prefetch xg contributions (DRAM; consumed after GEMM — latency hidden)
        float xg0 = g_xg[((size_t)t * BB + p2b0) * GG + xgrow0];
        float xg1 = g_xg[((size_t)t * BB + p2b1) * GG + xgrow1];

        // Load h (global -> padded smem). 16 float4/thread.
        const float4* hsrc = (t == 0) ? (const float4*)h0 : (const float4*)g_h[t & 1];
#pragma unroll
        for (int i = 0; i < 16; i++) {
            int idx = tid + NTH * i;
            int b = idx >> 7;
            int q = idx & 127;
            h4[b * 129 + q] = hsrc[idx];
        }
        __syncthreads();

        // --- GEMM: K-slice of 64 (16 float4 chunks), packed f32x2 ---
        unsigned long long acc0[8], acc1[8];
#pragma unroll
        for (int j = 0; j < 8; j++) { acc0[j] = 0ull; acc1[j] = 0ull; }

#pragma unroll
        for (int ci = 0; ci < 16; ci++) {
            ulonglong2 wv0 = ((const ulonglong2*)(wp0 + ci))[0];
            ulonglong2 wv1 = ((const ulonglong2*)(wp1 + ci))[0];
#pragma unroll
            for (int j = 0; j < 8; j++) {
                ulonglong2 hv = ((const ulonglong2*)(hp + j * 516 + ci))[0];
                acc0[j] = fma2(wv0.x, hv.x, acc0[j]);
                acc0[j] = fma2(wv0.y, hv.y, acc0[j]);
                acc1[j] = fma2(wv1.x, hv.x, acc1[j]);
                acc1[j] = fma2(wv1.y, hv.y, acc1[j]);
            }
        }

        // Horizontal sum + store partials (conflict-free: word%32 = 4rr+2p+4j+br)
        {
            float* rbase = red + wrp * (16 * 34);
#pragma unroll
            for (int j = 0; j < 8; j++) {
                int b = 4 * j + br;
                float x0, y0, x1, y1;
                upk2(acc0[j], x0, y0);
                upk2(acc1[j], x1, y1);
                rbase[r0 * 34 + b] = x0 + y0;
                rbase[r1 * 34 + b] = x1 + y1;
            }
        }
        __syncthreads();

        // --- Phase 2: split-K reduction + xg -> gates smem ---
        {
            float s0 = xg0, s1 = xg1;
            int i0 = p2r0 * 34 + p2b0;
            int i1 = p2r1 * 34 + p2b1;
#pragma unroll
            for (int w = 0; w < 8; w++) {
                s0 += red[w * (16 * 34) + i0];
                s1 += red[w * (16 * 34) + i1];
            }
            gates[p2r0 * 33 + p2b0] = s0;
            gates[p2r1 * 33 + p2b1] = s1;
        }
        __syncthreads();

        // --- Phase 3: activations + state update (128 threads: 4 cols x 32 b) ---
        if (tid < 128) {
            int cj = tid & 3;
            int b = tid >> 2;
            float gi = gates[(0  + cj) * 33 + b];
            float gf = gates[(4  + cj) * 33 + b];
            float gg = gates[(8  + cj) * 33 + b];
            float go = gates[(12 + cj) * 33 + b];
            float ig = sigf(gi);
            float fg = sigf(gf);
            float gt = tanhf(gg);
            float og = sigf(go);
            float cn = fmaf(fg, csm[tid], ig * gt);
            float hn = og * tanhf(cn);
            csm[tid] = cn;
            int col = col0 + cj;
            g_h[(t + 1) & 1][b * HH + col] = hn;
            out[((size_t)b * TT + t) * HH + col] = hn;
            if (t == TT - 1 && tails) {
                out[BTH + (long long)b * HH + col] = hn;
                out[BTH + (long long)BB * HH + (long long)b * HH + col] = cn;
            }
        }
        __threadfence();
        __syncthreads();
        // Grid barrier: monotonic counter (reset by kernel A each launch).
        if (tid == 0) {
            atomicAdd(&g_bar, 1);
            int target = NCTA * (t + 1);
            while (*vbar < target) __nanosleep(32);
            __threadfence();
        }
        __syncthreads();
    }
}

// ---------------------------------------------------------------------------
// Inputs (metadata order): x, h0, c0, W_ih, W_hh, b_ih, b_hh
// Output: concat(result[B,T,H], h_f[1,B,H], c_f[1,B,H])
// ---------------------------------------------------------------------------
extern "C" void kernel_launch(void* const* d_in, const int* in_sizes, int n_in,
                              void* d_out, int out_size) {
    const float* x   = (const float*)d_in[0];
    const float* h0  = (const float*)d_in[1];
    const float* c0  = (const float*)d_in[2];
    const float* Wih = (const float*)d_in[3];
    const float* Whh = (const float*)d_in[4];
    const float* bih = (const float*)d_in[5];
    const float* bhh = (const float*)d_in[6];
    float* out = (float*)d_out;

    // smem: h(66048) + w(33024) + red(17408) + gates(2112) + c(512)
    const int smem_b = (32 * 129 + 16 * 129) * 16 + (8 * 16 * 34 + 16 * 33 + 128) * 4;
    cudaFuncSetAttribute(lstm_rec_kernel, cudaFuncAttributeMaxDynamicSharedMemorySize, smem_b);

    dim3 gridA(GG / 64, (TT * BB) / 64);
    xg_gemm_kernel<<<gridA, 256>>>(x, Wih, bih, bhh);
    lstm_rec_kernel<<<NCTA, NTH, smem_b>>>(Whh, h0, c0, out, (long long)out_size);
}